// round 7
// baseline (speedup 1.0000x reference)
#include <cuda_runtime.h>
#include <math.h>

typedef unsigned long long ull;

// Problem constants
#define Bq   8
#define Cc   64
#define Hh   256
#define Ww   256
#define HWs  65536        // H*W
#define CHW  4194304      // C*H*W
#define CTAS_PER_BATCH 16
#define T_W  16           // w columns per CTA
#define GROUPS 16         // cout groups (4 couts each)
#define NW   256          // worker threads
#define THREADS 288       // 256 workers + 1 sync/fix warp
#define RSTRD 18          // packed doubles per channel row: [0]=left halo(0), [1..16]=data, [17]=right halo(0)

// smem carve (bytes)
#define OFF_WMAIN   0                          // 16*64*3 float4 = 49152
#define OFF_WFIXL   49152                      // 64*32 ull = 16384
#define OFF_WFIXR   65536                      // 16384
#define OFF_SD      81920                      // 64*18 ull = 9216
#define OFF_HALOL   91136                      // 64 ull = 512
#define OFF_HALOR   91648                      // 512
#define OFF_FIXL    92160                      // 32 ull = 256
#define OFF_FIXR    92416                      // 256
#define SMEM_BYTES  92672

// halo[b][r][side][parity][ch]: side 0 = CTA r's leftmost column, side 1 = rightmost
__device__ float        g_halo[Bq][CTAS_PER_BATCH][2][2][Cc];
// monotonic row counter per CTA; +256 per launch, uniform across CTAs
__device__ unsigned int g_flag[Bq][CTAS_PER_BATCH];

#define FMA2(acc, a, b) asm("fma.rn.f32x2 %0, %1, %2, %3;" : "=l"(acc) : "l"(a), "l"(b), "l"(acc))
#define ADD2(d, a, b)   asm("add.rn.f32x2 %0, %1, %2;"     : "=l"(d)   : "l"(a), "l"(b))

__device__ __forceinline__ ull pack2(float lo, float hi) {
    ull r;
    asm("mov.b64 %0, {%1, %2};" : "=l"(r)
        : "r"(__float_as_uint(lo)), "r"(__float_as_uint(hi)));
    return r;
}
__device__ __forceinline__ void unpack2(ull v, float& lo, float& hi) {
    unsigned int a, b2;
    asm("mov.b64 {%0, %1}, %2;" : "=r"(a), "=r"(b2) : "l"(v));
    lo = __uint_as_float(a); hi = __uint_as_float(b2);
}

__device__ __forceinline__ float tanh_fast(float x) {
    float ax = fabsf(x);
    float e  = __expf(2.0f * ax);
    float t  = 1.0f - 2.0f / (e + 1.0f);
    return copysignf(t, x);
}

__device__ __forceinline__ float vload_f(const float* p) {
    return *((volatile const float*)p);
}
__device__ __forceinline__ unsigned int vload_u(const unsigned int* p) {
    return *((volatile const unsigned int*)p);
}

__global__ void __launch_bounds__(THREADS, 1)
spatial_conv_kernel(const float* __restrict__ X,
                    const float* __restrict__ Wc,   // [64][64][3]
                    const float* __restrict__ bc,   // [64]
                    float* __restrict__ Y)
{
    extern __shared__ __align__(16) char smem[];
    float4* wMain  = reinterpret_cast<float4*>(smem + OFF_WMAIN);
    ull*    wFixL2 = reinterpret_cast<ull*>(smem + OFF_WFIXL);
    ull*    wFixR2 = reinterpret_cast<ull*>(smem + OFF_WFIXR);
    ull*    sD     = reinterpret_cast<ull*>(smem + OFF_SD);
    ull*    sHaloL2= reinterpret_cast<ull*>(smem + OFF_HALOL);
    ull*    sHaloR2= reinterpret_cast<ull*>(smem + OFF_HALOR);
    ull*    sFixL2 = reinterpret_cast<ull*>(smem + OFF_FIXL);
    ull*    sFixR2 = reinterpret_cast<ull*>(smem + OFF_FIXR);

    const int tid = threadIdx.x;
    const int b   = blockIdx.x >> 4;
    const int r   = blockIdx.x & 15;
    const bool worker = (tid < NW);
    const int w  = tid & 15;           // worker local column
    const int g  = (tid >> 4) & 15;    // worker cout group
    const int c0 = g * 4;
    const int wg = r * T_W + w;        // global column
    const int ls = tid - NW;           // sync-warp lane (valid when !worker)

    // ---- stage weights ----
    // wMain[(g*64+cin)*3+tap] = (K_tap for couts 4g..4g+3)
    for (int idx = tid; idx < GROUPS * Cc * 3; idx += THREADS) {
        int gg  = idx / 192;
        int rem = idx - gg * 192;
        int cin = rem / 3;
        int tap = rem - cin * 3;
        float4 v;
        v.x = Wc[((4 * gg + 0) * Cc + cin) * 3 + tap];
        v.y = Wc[((4 * gg + 1) * Cc + cin) * 3 + tap];
        v.z = Wc[((4 * gg + 2) * Cc + cin) * 3 + tap];
        v.w = Wc[((4 * gg + 3) * Cc + cin) * 3 + tap];
        wMain[idx] = v;
    }
    // fix weights, cout-pair packed: wFixL2[cin*32+p] = (W[2p][cin][0], W[2p+1][cin][0])
    for (int idx = tid; idx < 2 * Cc * 32; idx += THREADS) {
        int isR = idx >> 11;
        int rem = idx & 2047;
        int cin = rem >> 5;
        int p   = rem & 31;
        int tap = isR ? 2 : 0;
        float lo = Wc[((2 * p + 0) * Cc + cin) * 3 + tap];
        float hi = Wc[((2 * p + 1) * Cc + cin) * 3 + tap];
        (isR ? wFixR2 : wFixL2)[cin * 32 + p] = pack2(lo, hi);
    }
    // permanent zero halo slots in the duplicated row buffer
    for (int c = tid; c < Cc; c += THREADS) {
        sD[c * RSTRD + 0]  = 0ull;
        sD[c * RSTRD + 17] = 0ull;
    }
    // zero smem halos (edge CTAs never overwrite the missing side)
    if (!worker) {
        sHaloL2[ls] = 0ull; sHaloL2[ls + 32] = 0ull;
        sHaloR2[ls] = 0ull; sHaloR2[ls + 32] = 0ull;
    }

    unsigned int base = 0;
    if (!worker && ls < 2) base = vload_u(&g_flag[b][r]);

    const float* Xb = X + b * CHW;
    float*       Yb = Y + b * CHW;

    ull b01 = 0, b23 = 0;
    if (worker) {
        b01 = pack2(bc[c0 + 0], bc[c0 + 1]);
        b23 = pack2(bc[c0 + 2], bc[c0 + 3]);
    }

    // ---- row 0: Y[0] = X[0] ----
    if (worker) {
        float y0 = Xb[(c0 + 0) * HWs + wg];
        float y1 = Xb[(c0 + 1) * HWs + wg];
        float y2 = Xb[(c0 + 2) * HWs + wg];
        float y3 = Xb[(c0 + 3) * HWs + wg];
        Yb[(c0 + 0) * HWs + wg] = y0;
        Yb[(c0 + 1) * HWs + wg] = y1;
        Yb[(c0 + 2) * HWs + wg] = y2;
        Yb[(c0 + 3) * HWs + wg] = y3;
        sD[(c0 + 0) * RSTRD + 1 + w] = pack2(y0, y0);
        sD[(c0 + 1) * RSTRD + 1 + w] = pack2(y1, y1);
        sD[(c0 + 2) * RSTRD + 1 + w] = pack2(y2, y2);
        sD[(c0 + 3) * RSTRD + 1 + w] = pack2(y3, y3);
        if (w == 0) {
            float* hp = &g_halo[b][r][0][0][c0];
            hp[0] = y0; hp[1] = y1; hp[2] = y2; hp[3] = y3;
            __threadfence();
        }
        if (w == 15) {
            float* hp = &g_halo[b][r][1][0][c0];
            hp[0] = y0; hp[1] = y1; hp[2] = y2; hp[3] = y3;
            __threadfence();
        }
    }
    __syncthreads();
    if (!worker && ls == 0) atomicExch(&g_flag[b][r], base + 1u);

    // ---- recurrence ----
    for (int h = 1; h < Hh; h++) {
        if (worker) {
            // prefetch X for this row (hidden under the conv)
            const float* xrow = Xb + h * Ww + wg;
            float xi0 = xrow[(c0 + 0) * HWs];
            float xi1 = xrow[(c0 + 1) * HWs];
            float xi2 = xrow[(c0 + 2) * HWs];
            float xi3 = xrow[(c0 + 3) * HWs];

            ull a01 = b01, a23 = b23;
            const ull* xp = sD + w;
            const ulonglong2* kp =
                reinterpret_cast<const ulonglong2*>(wMain + g * 192);
#pragma unroll 16
            for (int cin = 0; cin < Cc; cin++) {
                ull xll = xp[0];
                ull xcc = xp[1];
                ull xrr = xp[2];
                ulonglong2 K0 = kp[0];
                ulonglong2 K1 = kp[1];
                ulonglong2 K2 = kp[2];
                FMA2(a01, K0.x, xll); FMA2(a23, K0.y, xll);
                FMA2(a01, K1.x, xcc); FMA2(a23, K1.y, xcc);
                FMA2(a01, K2.x, xrr); FMA2(a23, K2.y, xrr);
                xp += RSTRD;
                kp += 3;
            }

            __syncthreads();   // (A): fixups ready; all readers done with sD

            // edge fix add (packed); fix is exactly 0 for edge CTAs
            if (w == 0) {
                ull f01 = sFixL2[2 * g], f23 = sFixL2[2 * g + 1];
                ADD2(a01, a01, f01); ADD2(a23, a23, f23);
            }
            if (w == 15) {
                ull f01 = sFixR2[2 * g], f23 = sFixR2[2 * g + 1];
                ADD2(a01, a01, f01); ADD2(a23, a23, f23);
            }

            float a0, a1, a2, a3;
            unpack2(a01, a0, a1);
            unpack2(a23, a2, a3);

            float y0 = xi0 + tanh_fast(a0);
            float y1 = xi1 + tanh_fast(a1);
            float y2 = xi2 + tanh_fast(a2);
            float y3 = xi3 + tanh_fast(a3);

            float* yrow = Yb + h * Ww + wg;
            yrow[(c0 + 0) * HWs] = y0;
            yrow[(c0 + 1) * HWs] = y1;
            yrow[(c0 + 2) * HWs] = y2;
            yrow[(c0 + 3) * HWs] = y3;

            sD[(c0 + 0) * RSTRD + 1 + w] = pack2(y0, y0);
            sD[(c0 + 1) * RSTRD + 1 + w] = pack2(y1, y1);
            sD[(c0 + 2) * RSTRD + 1 + w] = pack2(y2, y2);
            sD[(c0 + 3) * RSTRD + 1 + w] = pack2(y3, y3);

            const int par = h & 1;
            if (w == 0) {
                float* hp = &g_halo[b][r][0][par][c0];
                hp[0] = y0; hp[1] = y1; hp[2] = y2; hp[3] = y3;
                __threadfence();
            }
            if (w == 15) {
                float* hp = &g_halo[b][r][1][par][c0];
                hp[0] = y0; hp[1] = y1; hp[2] = y2; hp[3] = y3;
                __threadfence();
            }
            __syncthreads();   // (B)
        } else {
            // -------- sync/fix warp --------
            unsigned int tgt = base + (unsigned int)h;
            if (ls == 0 && r > 0) {
                while ((int)(vload_u(&g_flag[b][r - 1]) - tgt) < 0) { }
            }
            if (ls == 1 && r < 15) {
                while ((int)(vload_u(&g_flag[b][r + 1]) - tgt) < 0) { }
            }
            __syncwarp();

            const int par = (h - 1) & 1;
            if (r > 0) {
                float v0 = vload_f(&g_halo[b][r - 1][1][par][ls]);
                float v1 = vload_f(&g_halo[b][r - 1][1][par][ls + 32]);
                sHaloL2[ls]      = pack2(v0, v0);
                sHaloL2[ls + 32] = pack2(v1, v1);
            }
            if (r < 15) {
                float v0 = vload_f(&g_halo[b][r + 1][0][par][ls]);
                float v1 = vload_f(&g_halo[b][r + 1][0][par][ls + 32]);
                sHaloR2[ls]      = pack2(v0, v0);
                sHaloR2[ls + 32] = pack2(v1, v1);
            }
            __syncwarp();

            // fix dot products: lane ls covers cout pair (2ls, 2ls+1)
            ull fl = 0ull, fr = 0ull;
            const ull* wl = wFixL2 + ls;
            const ull* wr = wFixR2 + ls;
#pragma unroll 8
            for (int cin = 0; cin < Cc; cin++) {
                ull hl = sHaloL2[cin];
                ull hr = sHaloR2[cin];
                FMA2(fl, wl[0], hl);
                FMA2(fr, wr[0], hr);
                wl += 32;
                wr += 32;
            }
            sFixL2[ls] = fl;
            sFixR2[ls] = fr;

            __syncthreads();   // (A)
            __syncthreads();   // (B)
            if (ls == 0) atomicExch(&g_flag[b][r], base + (unsigned int)h + 1u);
        }
    }
}

extern "C" void kernel_launch(void* const* d_in, const int* in_sizes, int n_in,
                              void* d_out, int out_size)
{
    const float* X  = (const float*)d_in[0];
    const float* Wc = (const float*)d_in[1];
    const float* bc = (const float*)d_in[2];
    float*       Y  = (float*)d_out;
    (void)in_sizes; (void)n_in; (void)out_size;

    cudaFuncSetAttribute(spatial_conv_kernel,
                         cudaFuncAttributeMaxDynamicSharedMemorySize, SMEM_BYTES);

    spatial_conv_kernel<<<Bq * CTAS_PER_BATCH, THREADS, SMEM_BYTES>>>(X, Wc, bc, Y);
}